// round 4
// baseline (speedup 1.0000x reference)
#include <cuda_runtime.h>
#include <cstdint>

#define BATCH 16384
#define NEGK  20
#define NT    21              // 1 pos + 20 neg
#define NROWS 22              // + center row
#define DIM   128
#define ROW_BYTES 512
#define WPB   4               // warps per block
#define NB    16              // batch elements per warp
#define CTAS  (BATCH / (WPB * NB))        // 256
#define STAGE_BYTES (NROWS * ROW_BYTES)   // 11264
#define WARP_SMEM   (2 * STAGE_BYTES)     // 22528 (double buffered)
#define SMEM_BYTES  (WPB * WARP_SMEM)     // 90112

__global__ void zero_out_kernel(float* out) { out[0] = 0.0f; }

__device__ __forceinline__ void cp16(uint32_t dst_smem, const void* src_gmem) {
    asm volatile("cp.async.cg.shared.global [%0], [%1], 16;"
                 :: "r"(dst_smem), "l"(src_gmem) : "memory");
}
__device__ __forceinline__ void cp_commit() {
    asm volatile("cp.async.commit_group;" ::: "memory");
}
__device__ __forceinline__ void cp_wait1() {
    asm volatile("cp.async.wait_group 1;" ::: "memory");
}
__device__ __forceinline__ void cp_wait0() {
    asm volatile("cp.async.wait_group 0;" ::: "memory");
}

extern __shared__ char smem_raw[];

// Per-lane index fetch for batch element b: lane 0 -> pos, lanes 1..20 -> neg,
// lane 21 -> center. Other lanes get 0 (unused).
__device__ __forceinline__ int load_idx(int b, int lane,
                                        const int* __restrict__ pos,
                                        const int* __restrict__ neg,
                                        const int* __restrict__ center) {
    int v = 0;
    if (lane == 0)        v = pos[b];
    else if (lane < NT)   v = neg[b * NEGK + lane - 1];
    else if (lane == NT)  v = center[b];
    return v;
}

__global__ void __launch_bounds__(WPB * 32)
i2v_loss_kernel(const int* __restrict__ center,
                const int* __restrict__ pos,
                const int* __restrict__ neg,
                const float* __restrict__ W_in,
                const float* __restrict__ W_out,
                float* __restrict__ out)
{
    const unsigned FULL = 0xffffffffu;
    const int lane = threadIdx.x & 31;
    const int wid  = threadIdx.x >> 5;

    const uint32_t sbase = (uint32_t)__cvta_generic_to_shared(smem_raw);
    const uint32_t wbase = sbase + wid * WARP_SMEM;

    const int b0 = (blockIdx.x * WPB + wid) * NB;

    // ---- issue all 22 row copies for element i into stage (i&1) ----------
    auto issue = [&](int i, int my_idx) {
        const uint32_t stage = wbase + (i & 1) * STAGE_BYTES;
        #pragma unroll
        for (int k = 0; k < NROWS; ++k) {
            const int idx = __shfl_sync(FULL, my_idx, k);
            const float* base = (k < NT) ? W_out : W_in;
            const float* src  = base + (size_t)idx * DIM + 4 * lane;  // this lane's 16B
            cp16(stage + k * ROW_BYTES + lane * 16, src);
        }
        cp_commit();
    };

    // ---- software pipeline: idx prefetched 1 elem ahead, rows 1 stage ahead
    int cur_idx = load_idx(b0 + 0, lane, pos, neg, center);
    issue(0, cur_idx);
    int nxt_idx = (NB > 1) ? load_idx(b0 + 1, lane, pos, neg, center) : 0;

    float lloss = 0.0f;

    for (int i = 0; i < NB; ++i) {
        if (i + 1 < NB) {
            issue(i + 1, nxt_idx);
            if (i + 2 < NB)
                nxt_idx = load_idx(b0 + i + 2, lane, pos, neg, center);
            cp_wait1();   // stage i complete (i+1 may still be in flight)
        } else {
            cp_wait0();
        }

        const uint32_t stage = wbase + (i & 1) * STAGE_BYTES;

        // center row: this lane's 16B (bytes it copied itself)
        float4 c;
        asm volatile("ld.shared.v4.f32 {%0,%1,%2,%3}, [%4];"
                     : "=f"(c.x), "=f"(c.y), "=f"(c.z), "=f"(c.w)
                     : "r"(stage + NT * ROW_BYTES + lane * 16));

        float p[NT];
        #pragma unroll
        for (int k = 0; k < NT; ++k) {
            float4 v;
            asm volatile("ld.shared.v4.f32 {%0,%1,%2,%3}, [%4];"
                         : "=f"(v.x), "=f"(v.y), "=f"(v.z), "=f"(v.w)
                         : "r"(stage + k * ROW_BYTES + lane * 16));
            p[k] = c.x * v.x + c.y * v.y + c.z * v.z + c.w * v.w;
        }

        // 21 interleaved butterfly reductions (chains pipeline)
        #pragma unroll
        for (int off = 16; off > 0; off >>= 1) {
            #pragma unroll
            for (int k = 0; k < NT; ++k)
                p[k] += __shfl_xor_sync(FULL, p[k], off);
        }

        // lane k owns target k's loss (parallel MUFU across lanes)
        float mine = 0.0f;
        #pragma unroll
        for (int k = 0; k < NT; ++k)
            if (lane == k) mine = p[k];

        if (lane < NT) {
            const float s   = (lane == 0) ? mine : -mine;
            const float sig = 1.0f / (1.0f + __expf(-s));
            lloss += -logf(sig + 1e-10f);
        }
    }

    // final warp reduce of accumulated loss, one atomic per warp
    #pragma unroll
    for (int off = 16; off > 0; off >>= 1)
        lloss += __shfl_xor_sync(FULL, lloss, off);

    if (lane == 0)
        atomicAdd(out, lloss * (1.0f / (float)BATCH));
}

extern "C" void kernel_launch(void* const* d_in, const int* in_sizes, int n_in,
                              void* d_out, int out_size)
{
    const int*   center = (const int*)  d_in[0];
    const int*   pos    = (const int*)  d_in[1];
    const int*   neg    = (const int*)  d_in[2];
    const float* W_in   = (const float*)d_in[3];
    const float* W_out  = (const float*)d_in[4];
    float* out = (float*)d_out;

    cudaFuncSetAttribute(i2v_loss_kernel,
                         cudaFuncAttributeMaxDynamicSharedMemorySize, SMEM_BYTES);

    zero_out_kernel<<<1, 1>>>(out);
    i2v_loss_kernel<<<CTAS, WPB * 32, SMEM_BYTES>>>(center, pos, neg,
                                                    W_in, W_out, out);
}

// round 5
// speedup vs baseline: 1.0417x; 1.0417x over previous
#include <cuda_runtime.h>
#include <cstdint>

#define BATCH 16384
#define NEGK  20
#define NT    21              // 1 pos + 20 neg
#define NROWS 22              // + center row
#define DIM   128
#define ROW_BYTES 512
#define WPB   4               // warps per CTA
#define CTAS  296             // 2 resident CTAs per SM, all 148 SMs balanced
#define NWARPS (CTAS * WPB)   // 1184 persistent warps, grid-stride over batch
#define STAGE_BYTES (NROWS * ROW_BYTES)   // 11264
#define WARP_SMEM   (2 * STAGE_BYTES)     // 22528 (double buffered)
#define SMEM_BYTES  (WPB * WARP_SMEM)     // 90112

__global__ void zero_out_kernel(float* out) { out[0] = 0.0f; }

__device__ __forceinline__ void cp16(uint32_t dst_smem, const void* src_gmem) {
    asm volatile("cp.async.cg.shared.global [%0], [%1], 16;"
                 :: "r"(dst_smem), "l"(src_gmem) : "memory");
}
__device__ __forceinline__ void cp_commit() {
    asm volatile("cp.async.commit_group;" ::: "memory");
}
__device__ __forceinline__ void cp_wait1() {
    asm volatile("cp.async.wait_group 1;" ::: "memory");
}
__device__ __forceinline__ void cp_wait0() {
    asm volatile("cp.async.wait_group 0;" ::: "memory");
}

extern __shared__ char smem_raw[];

// Lane 0 -> pos, lanes 1..20 -> neg, lane 21 -> center.
__device__ __forceinline__ int load_idx(int b, int lane,
                                        const int* __restrict__ pos,
                                        const int* __restrict__ neg,
                                        const int* __restrict__ center) {
    int v = 0;
    if (lane == 0)        v = pos[b];
    else if (lane < NT)   v = neg[b * NEGK + lane - 1];
    else if (lane == NT)  v = center[b];
    return v;
}

__global__ void __launch_bounds__(WPB * 32)
i2v_loss_kernel(const int* __restrict__ center,
                const int* __restrict__ pos,
                const int* __restrict__ neg,
                const float* __restrict__ W_in,
                const float* __restrict__ W_out,
                float* __restrict__ out)
{
    const unsigned FULL = 0xffffffffu;
    const int lane = threadIdx.x & 31;
    const int wid  = threadIdx.x >> 5;
    const int wgid = blockIdx.x * WPB + wid;   // global warp id

    const uint32_t sbase = (uint32_t)__cvta_generic_to_shared(smem_raw);
    const uint32_t wbase = sbase + wid * WARP_SMEM;

    // Issue all 22 row copies for a batch element into stage buf (0/1).
    auto issue = [&](int buf, int my_idx) {
        const uint32_t stage = wbase + buf * STAGE_BYTES;
        #pragma unroll
        for (int k = 0; k < NROWS; ++k) {
            const int idx = __shfl_sync(FULL, my_idx, k);
            const float* base = (k < NT) ? W_out : W_in;
            cp16(stage + k * ROW_BYTES + lane * 16,
                 base + (size_t)idx * DIM + 4 * lane);
        }
        cp_commit();
    };

    float lloss = 0.0f;

    // Grid-stride software pipeline: element e in buf, e+NWARPS prefetching.
    int e = wgid;
    int buf = 0;
    if (e < BATCH) {
        int idx_cur = load_idx(e, lane, pos, neg, center);
        issue(buf, idx_cur);
        int nxt = e + NWARPS;
        int idx_nxt = (nxt < BATCH) ? load_idx(nxt, lane, pos, neg, center) : 0;

        while (e < BATCH) {
            const int has_next = (e + NWARPS < BATCH);
            if (has_next) {
                issue(buf ^ 1, idx_nxt);
                const int nn = e + 2 * NWARPS;
                if (nn < BATCH) idx_nxt = load_idx(nn, lane, pos, neg, center);
                cp_wait1();        // current stage done; next still in flight
            } else {
                cp_wait0();
            }

            const uint32_t stage = wbase + buf * STAGE_BYTES;

            float4 c;
            asm volatile("ld.shared.v4.f32 {%0,%1,%2,%3}, [%4];"
                         : "=f"(c.x), "=f"(c.y), "=f"(c.z), "=f"(c.w)
                         : "r"(stage + NT * ROW_BYTES + lane * 16));

            float p[NT];
            #pragma unroll
            for (int k = 0; k < NT; ++k) {
                float4 v;
                asm volatile("ld.shared.v4.f32 {%0,%1,%2,%3}, [%4];"
                             : "=f"(v.x), "=f"(v.y), "=f"(v.z), "=f"(v.w)
                             : "r"(stage + k * ROW_BYTES + lane * 16));
                p[k] = c.x * v.x + c.y * v.y + c.z * v.z + c.w * v.w;
            }

            #pragma unroll
            for (int off = 16; off > 0; off >>= 1) {
                #pragma unroll
                for (int k = 0; k < NT; ++k)
                    p[k] += __shfl_xor_sync(FULL, p[k], off);
            }

            float mine = 0.0f;
            #pragma unroll
            for (int k = 0; k < NT; ++k)
                if (lane == k) mine = p[k];

            if (lane < NT) {
                const float s   = (lane == 0) ? mine : -mine;
                const float sig = 1.0f / (1.0f + __expf(-s));
                lloss += -logf(sig + 1e-10f);
            }

            e += NWARPS;
            buf ^= 1;
        }
    }

    // warp reduce accumulated loss, one atomic per warp
    #pragma unroll
    for (int off = 16; off > 0; off >>= 1)
        lloss += __shfl_xor_sync(FULL, lloss, off);

    if (lane == 0)
        atomicAdd(out, lloss * (1.0f / (float)BATCH));
}

extern "C" void kernel_launch(void* const* d_in, const int* in_sizes, int n_in,
                              void* d_out, int out_size)
{
    const int*   center = (const int*)  d_in[0];
    const int*   pos    = (const int*)  d_in[1];
    const int*   neg    = (const int*)  d_in[2];
    const float* W_in   = (const float*)d_in[3];
    const float* W_out  = (const float*)d_in[4];
    float* out = (float*)d_out;

    cudaFuncSetAttribute(i2v_loss_kernel,
                         cudaFuncAttributeMaxDynamicSharedMemorySize, SMEM_BYTES);

    zero_out_kernel<<<1, 1>>>(out);
    i2v_loss_kernel<<<CTAS, WPB * 32, SMEM_BYTES>>>(center, pos, neg,
                                                    W_in, W_out, out);
}